// round 5
// baseline (speedup 1.0000x reference)
#include <cuda_runtime.h>
#include <cuda_fp16.h>

#define NODES_MAX 100000
#define NPER 12
#define ROWH 16   // padded fp16 row: 16 halves = 32 B = one L2 sector

__device__ int    g_deg[NODES_MAX];
__device__ float  g_dinv[NODES_MAX];
__device__ __align__(32) __half g_yh[NODES_MAX * ROWH];    // y = x * dinv_src, fp16
__device__ __align__(32) __half g_acch[NODES_MAX * ROWH];  // fp16 accumulator
// folded coefficients: az[4], bz[4], ah[4], bh[4], pr[12]  = 28 floats
__device__ float g_cf[32];

// ---------------- K0: zero deg + compute folded coefficients ----------------
__global__ void k_zero(int n_nodes,
                       const float* __restrict__ cz_w, const float* __restrict__ cz_b,
                       const float* __restrict__ lz_w, const float* __restrict__ lz_b,
                       const float* __restrict__ ch_w, const float* __restrict__ ch_b,
                       const float* __restrict__ lh_w, const float* __restrict__ lh_b,
                       const float* __restrict__ att) {
    int i = blockIdx.x * blockDim.x + threadIdx.x;
    if (i < n_nodes) g_deg[i] = 0;
    if (blockIdx.x == 0 && threadIdx.x == 0) {
        for (int c = 0; c < 4; c++) {
            float a = 0.f, b = lz_b[c];
            float a2 = 0.f, b2 = lh_b[c];
            for (int k = 0; k < 4; k++) {
                float lz = lz_w[k * 4 + c];
                float lh = lh_w[k * 4 + c];
                a  += cz_w[k] * lz;
                b  += cz_b[k] * lz;
                a2 += ch_w[k] * lh;
                b2 += ch_b[k] * lh;
            }
            g_cf[c] = a;       g_cf[4 + c] = b;
            g_cf[8 + c] = a2;  g_cf[12 + c] = b2;
        }
        float m = -1e30f;
        for (int p = 0; p < NPER; p++) m = fmaxf(m, att[p]);
        float sum = 0.f;
        float e[NPER];
        for (int p = 0; p < NPER; p++) { e[p] = __expf(att[p] - m); sum += e[p]; }
        float inv = 1.0f / sum;
        for (int p = 0; p < NPER; p++) g_cf[16 + p] = e[p] * inv;
    }
}

// ---------------- K1: degree count (int4 vectorized) ----------------
__global__ void k_deg(const int* __restrict__ dst, int E) {
    int i = blockIdx.x * blockDim.x + threadIdx.x;
    int e4 = E >> 2;
    if (i < e4) {
        int4 d = ((const int4*)dst)[i];
        atomicAdd(&g_deg[d.x], 1);
        atomicAdd(&g_deg[d.y], 1);
        atomicAdd(&g_deg[d.z], 1);
        atomicAdd(&g_deg[d.w], 1);
    } else if (i == e4) {
        for (int r = e4 * 4; r < E; r++) atomicAdd(&g_deg[dst[r]], 1);
    }
}

// ---------------- K2: dinv + scaled x into padded fp16 rows (+ zero acc) ----------------
__global__ void k_prep(const float* __restrict__ x, int n) {
    int i = blockIdx.x * blockDim.x + threadIdx.x;
    if (i >= n) return;
    float dinv = rsqrtf((float)(g_deg[i] + 1));  // +1 for self loop
    g_dinv[i] = dinv;
    const float4* xr = (const float4*)(x + (size_t)i * NPER);
    float4 a = xr[0], b = xr[1], c = xr[2];
    __half2 h0 = __floats2half2_rn(a.x * dinv, a.y * dinv);
    __half2 h1 = __floats2half2_rn(a.z * dinv, a.w * dinv);
    __half2 h2 = __floats2half2_rn(b.x * dinv, b.y * dinv);
    __half2 h3 = __floats2half2_rn(b.z * dinv, b.w * dinv);
    __half2 h4 = __floats2half2_rn(c.x * dinv, c.y * dinv);
    __half2 h5 = __floats2half2_rn(c.z * dinv, c.w * dinv);
    uint4* row = (uint4*)(g_yh + (size_t)i * ROWH);
    uint4 lo;
    lo.x = *(unsigned*)&h0;
    lo.y = *(unsigned*)&h1;
    lo.z = *(unsigned*)&h2;
    lo.w = *(unsigned*)&h3;
    row[0] = lo;
    uint4 hi;
    hi.x = *(unsigned*)&h4;
    hi.y = *(unsigned*)&h5;
    hi.z = 0;
    hi.w = 0;
    row[1] = hi;
    // zero this node's accumulator row (fused; was a separate pass)
    uint4* arow = (uint4*)(g_acch + (size_t)i * ROWH);
    arow[0] = make_uint4(0, 0, 0, 0);
    arow[1] = make_uint4(0, 0, 0, 0);
}

// ---------------- K3: edge scatter (the hot kernel) ----------------
__global__ void k_scatter(const int* __restrict__ src, const int* __restrict__ dst, int E) {
    int e = blockIdx.x * blockDim.x + threadIdx.x;
    if (e >= E) return;
    int s = src[e];
    int d = dst[e];
    const uint4* yr = (const uint4*)(g_yh + (size_t)s * ROWH);
    uint4 lo = __ldg(yr + 0);
    uint2 hi = __ldg((const uint2*)(yr + 1));
    __half* ap = g_acch + (size_t)d * ROWH;
    asm volatile("red.global.add.noftz.v4.f16x2 [%0], {%1,%2,%3,%4};"
                 :: "l"(ap), "r"(lo.x), "r"(lo.y), "r"(lo.z), "r"(lo.w)
                 : "memory");
    asm volatile("red.global.add.noftz.v2.f16x2 [%0], {%1,%2};"
                 :: "l"(ap + 8), "r"(hi.x), "r"(hi.y)
                 : "memory");
}

// ---------------- K4: per-node epilogue ----------------
__device__ __forceinline__ float fsigmoid(float x) {
    return 1.0f / (1.0f + __expf(-x));
}
__device__ __forceinline__ float ftanh(float x) {
    return 1.0f - 2.0f / (1.0f + __expf(2.0f * x));
}

__global__ void k_final(const float* __restrict__ x,
                        const float* __restrict__ ow, const float* __restrict__ ob,
                        float* __restrict__ out, int n) {
    int i = blockIdx.x * blockDim.x + threadIdx.x;
    if (i >= n) return;

    float az[4], bz[4], ah[4], bh[4], pr[NPER];
#pragma unroll
    for (int c = 0; c < 4; c++) {
        az[c] = __ldg(&g_cf[c]);
        bz[c] = __ldg(&g_cf[4 + c]);
        ah[c] = __ldg(&g_cf[8 + c]);
        bh[c] = __ldg(&g_cf[12 + c]);
    }
#pragma unroll
    for (int p = 0; p < NPER; p++) pr[p] = __ldg(&g_cf[16 + p]);

    float dinv = g_dinv[i];
    float d2 = dinv * dinv;

    const uint4* ar = (const uint4*)(g_acch + (size_t)i * ROWH);
    uint4 alo = ar[0];
    uint2 ahi = *(const uint2*)(ar + 1);
    float av[NPER];
    {
        float2 t;
        t = __half22float2(*(__half2*)&alo.x); av[0] = t.x; av[1] = t.y;
        t = __half22float2(*(__half2*)&alo.y); av[2] = t.x; av[3] = t.y;
        t = __half22float2(*(__half2*)&alo.z); av[4] = t.x; av[5] = t.y;
        t = __half22float2(*(__half2*)&alo.w); av[6] = t.x; av[7] = t.y;
        t = __half22float2(*(__half2*)&ahi.x); av[8] = t.x; av[9] = t.y;
        t = __half22float2(*(__half2*)&ahi.y); av[10] = t.x; av[11] = t.y;
    }

    const float4* xr = (const float4*)(x + (size_t)i * NPER);
    float xv[NPER];
#pragma unroll
    for (int q = 0; q < 3; q++) {
        float4 v = xr[q];
        xv[q * 4 + 0] = v.x; xv[q * 4 + 1] = v.y;
        xv[q * 4 + 2] = v.z; xv[q * 4 + 3] = v.w;
    }

    float H[4] = {0.f, 0.f, 0.f, 0.f};
#pragma unroll
    for (int p = 0; p < NPER; p++) {
        float sp = fmaf(dinv, av[p], d2 * xv[p]);  // edge sum + self loop (fp32)
        float w = pr[p];
#pragma unroll
        for (int c = 0; c < 4; c++) {
            float zc = fsigmoid(fmaf(sp, az[c], bz[c]));
            float th = ftanh(fmaf(sp, ah[c], bh[c]));
            H[c] = fmaf(w * (1.0f - zc), th, H[c]);
        }
    }

    float o[NPER];
#pragma unroll
    for (int f = 0; f < NPER; f++) {
        float v = __ldg(&ob[f]);
#pragma unroll
        for (int c = 0; c < 4; c++) v = fmaf(H[c], __ldg(&ow[c * NPER + f]), v);
        o[f] = v;
    }
    float4* orow = (float4*)(out + (size_t)i * NPER);
    orow[0] = make_float4(o[0], o[1], o[2], o[3]);
    orow[1] = make_float4(o[4], o[5], o[6], o[7]);
    orow[2] = make_float4(o[8], o[9], o[10], o[11]);
}

// ---------------- launch ----------------
extern "C" void kernel_launch(void* const* d_in, const int* in_sizes, int n_in,
                              void* d_out, int out_size) {
    const float* x  = (const float*)d_in[0];
    const int*   ei = (const int*)d_in[1];
    const float* cz_w = (const float*)d_in[2];
    const float* cz_b = (const float*)d_in[3];
    const float* lz_w = (const float*)d_in[4];
    const float* lz_b = (const float*)d_in[5];
    // d_in[6..9] = conv_r / lin_r : dead (multiplied by H0 == 0)
    const float* ch_w = (const float*)d_in[10];
    const float* ch_b = (const float*)d_in[11];
    const float* lh_w = (const float*)d_in[12];
    const float* lh_b = (const float*)d_in[13];
    const float* att  = (const float*)d_in[14];
    const float* ow   = (const float*)d_in[15];
    const float* ob   = (const float*)d_in[16];
    float* out = (float*)d_out;

    int N = in_sizes[0] / NPER;
    int E = in_sizes[1] / 2;
    const int* src = ei;
    const int* dst = ei + E;

    const int TB = 256;
    k_zero<<<(N + TB - 1) / TB, TB>>>(N, cz_w, cz_b, lz_w, lz_b,
                                      ch_w, ch_b, lh_w, lh_b, att);
    int degThreads = (E >> 2) + 1;
    k_deg<<<(degThreads + TB - 1) / TB, TB>>>(dst, E);
    k_prep<<<(N + TB - 1) / TB, TB>>>(x, N);
    k_scatter<<<(E + TB - 1) / TB, TB>>>(src, dst, E);
    k_final<<<(N + TB - 1) / TB, TB>>>(x, ow, ob, out, N);
}

// round 6
// speedup vs baseline: 1.0320x; 1.0320x over previous
#include <cuda_runtime.h>
#include <cuda_fp16.h>

#define NODES_MAX 100000
#define NPER 12
#define ROWH 16   // padded fp16 row: 16 halves = 32 B = one L2 sector

__device__ int    g_deg[NODES_MAX];          // zero-init at load; k_final re-zeroes each call
__device__ float  g_dinv[NODES_MAX];
__device__ __align__(32) __half g_yh[NODES_MAX * ROWH];    // y = x * dinv_src, fp16
__device__ __align__(32) __half g_acch[NODES_MAX * ROWH];  // fp16 accumulator
// folded coefficients: az[4], bz[4], ah[4], bh[4], pr[12]  = 28 floats
__device__ float g_cf[32];

// ---------------- K1: degree count (int4 vectorized) + coef fold ----------------
__global__ void k_deg(const int* __restrict__ dst, int E,
                      const float* __restrict__ cz_w, const float* __restrict__ cz_b,
                      const float* __restrict__ lz_w, const float* __restrict__ lz_b,
                      const float* __restrict__ ch_w, const float* __restrict__ ch_b,
                      const float* __restrict__ lh_w, const float* __restrict__ lh_b,
                      const float* __restrict__ att) {
    int i = blockIdx.x * blockDim.x + threadIdx.x;
    int e4 = E >> 2;
    if (i < e4) {
        int4 d = ((const int4*)dst)[i];
        atomicAdd(&g_deg[d.x], 1);
        atomicAdd(&g_deg[d.y], 1);
        atomicAdd(&g_deg[d.z], 1);
        atomicAdd(&g_deg[d.w], 1);
    } else if (i == e4) {
        for (int r = e4 * 4; r < E; r++) atomicAdd(&g_deg[dst[r]], 1);
    }
    if (blockIdx.x == 0 && threadIdx.x == 0) {
        // fold rank-1 GCN + linear into affine pairs per gate/channel
        for (int c = 0; c < 4; c++) {
            float a = 0.f, b = lz_b[c];
            float a2 = 0.f, b2 = lh_b[c];
            for (int k = 0; k < 4; k++) {
                float lz = lz_w[k * 4 + c];
                float lh = lh_w[k * 4 + c];
                a  += cz_w[k] * lz;
                b  += cz_b[k] * lz;
                a2 += ch_w[k] * lh;
                b2 += ch_b[k] * lh;
            }
            g_cf[c] = a;       g_cf[4 + c] = b;
            g_cf[8 + c] = a2;  g_cf[12 + c] = b2;
        }
        float m = -1e30f;
        for (int p = 0; p < NPER; p++) m = fmaxf(m, att[p]);
        float sum = 0.f;
        float e[NPER];
        for (int p = 0; p < NPER; p++) { e[p] = __expf(att[p] - m); sum += e[p]; }
        float inv = 1.0f / sum;
        for (int p = 0; p < NPER; p++) g_cf[16 + p] = e[p] * inv;
    }
}

// ---------------- K2: dinv + scaled x into padded fp16 rows (+ zero acc) ----------------
__global__ void k_prep(const float* __restrict__ x, int n) {
    int i = blockIdx.x * blockDim.x + threadIdx.x;
    if (i >= n) return;
    float dinv = rsqrtf((float)(g_deg[i] + 1));  // +1 for self loop
    g_dinv[i] = dinv;
    const float4* xr = (const float4*)(x + (size_t)i * NPER);
    float4 a = xr[0], b = xr[1], c = xr[2];
    __half2 h0 = __floats2half2_rn(a.x * dinv, a.y * dinv);
    __half2 h1 = __floats2half2_rn(a.z * dinv, a.w * dinv);
    __half2 h2 = __floats2half2_rn(b.x * dinv, b.y * dinv);
    __half2 h3 = __floats2half2_rn(b.z * dinv, b.w * dinv);
    __half2 h4 = __floats2half2_rn(c.x * dinv, c.y * dinv);
    __half2 h5 = __floats2half2_rn(c.z * dinv, c.w * dinv);
    uint4* row = (uint4*)(g_yh + (size_t)i * ROWH);
    uint4 lo;
    lo.x = *(unsigned*)&h0;
    lo.y = *(unsigned*)&h1;
    lo.z = *(unsigned*)&h2;
    lo.w = *(unsigned*)&h3;
    row[0] = lo;
    uint4 hi;
    hi.x = *(unsigned*)&h4;
    hi.y = *(unsigned*)&h5;
    hi.z = 0;
    hi.w = 0;
    row[1] = hi;
    // zero this node's accumulator row
    uint4* arow = (uint4*)(g_acch + (size_t)i * ROWH);
    arow[0] = make_uint4(0, 0, 0, 0);
    arow[1] = make_uint4(0, 0, 0, 0);
}

// ---------------- K3: edge scatter, 4 edges/thread ----------------
__device__ __forceinline__ void scatter_one(int s, int d, uint4 lo, uint2 hi) {
    __half* ap = g_acch + (size_t)d * ROWH;
    asm volatile("red.global.add.noftz.v4.f16x2 [%0], {%1,%2,%3,%4};"
                 :: "l"(ap), "r"(lo.x), "r"(lo.y), "r"(lo.z), "r"(lo.w)
                 : "memory");
    asm volatile("red.global.add.noftz.v2.f16x2 [%0], {%1,%2};"
                 :: "l"(ap + 8), "r"(hi.x), "r"(hi.y)
                 : "memory");
}

__global__ void k_scatter(const int* __restrict__ src, const int* __restrict__ dst, int E) {
    int t = blockIdx.x * blockDim.x + threadIdx.x;
    int e4 = E >> 2;
    if (t < e4) {
        int4 s4 = ((const int4*)src)[t];
        int4 d4 = ((const int4*)dst)[t];
        // issue all gathers first for MLP
        const uint4* y0 = (const uint4*)(g_yh + (size_t)s4.x * ROWH);
        const uint4* y1 = (const uint4*)(g_yh + (size_t)s4.y * ROWH);
        const uint4* y2 = (const uint4*)(g_yh + (size_t)s4.z * ROWH);
        const uint4* y3 = (const uint4*)(g_yh + (size_t)s4.w * ROWH);
        uint4 lo0 = __ldg(y0); uint2 hi0 = __ldg((const uint2*)(y0 + 1));
        uint4 lo1 = __ldg(y1); uint2 hi1 = __ldg((const uint2*)(y1 + 1));
        uint4 lo2 = __ldg(y2); uint2 hi2 = __ldg((const uint2*)(y2 + 1));
        uint4 lo3 = __ldg(y3); uint2 hi3 = __ldg((const uint2*)(y3 + 1));
        scatter_one(s4.x, d4.x, lo0, hi0);
        scatter_one(s4.y, d4.y, lo1, hi1);
        scatter_one(s4.z, d4.z, lo2, hi2);
        scatter_one(s4.w, d4.w, lo3, hi3);
    } else if (t == e4) {
        for (int r = e4 * 4; r < E; r++) {
            int s = src[r], d = dst[r];
            const uint4* yr = (const uint4*)(g_yh + (size_t)s * ROWH);
            uint4 lo = __ldg(yr); uint2 hi = __ldg((const uint2*)(yr + 1));
            scatter_one(s, d, lo, hi);
        }
    }
}

// ---------------- K4: per-node epilogue (+ re-zero deg for next call) ----------------
__device__ __forceinline__ float fsigmoid(float x) {
    return 1.0f / (1.0f + __expf(-x));
}
__device__ __forceinline__ float ftanh(float x) {
    return 1.0f - 2.0f / (1.0f + __expf(2.0f * x));
}

__global__ void k_final(const float* __restrict__ x,
                        const float* __restrict__ ow, const float* __restrict__ ob,
                        float* __restrict__ out, int n) {
    int i = blockIdx.x * blockDim.x + threadIdx.x;
    if (i >= n) return;

    g_deg[i] = 0;  // leave deg zeroed for the next kernel_launch call

    float az[4], bz[4], ah[4], bh[4], pr[NPER];
#pragma unroll
    for (int c = 0; c < 4; c++) {
        az[c] = __ldg(&g_cf[c]);
        bz[c] = __ldg(&g_cf[4 + c]);
        ah[c] = __ldg(&g_cf[8 + c]);
        bh[c] = __ldg(&g_cf[12 + c]);
    }
#pragma unroll
    for (int p = 0; p < NPER; p++) pr[p] = __ldg(&g_cf[16 + p]);

    float dinv = g_dinv[i];
    float d2 = dinv * dinv;

    const uint4* ar = (const uint4*)(g_acch + (size_t)i * ROWH);
    uint4 alo = ar[0];
    uint2 ahi = *(const uint2*)(ar + 1);
    float av[NPER];
    {
        float2 t;
        t = __half22float2(*(__half2*)&alo.x); av[0] = t.x; av[1] = t.y;
        t = __half22float2(*(__half2*)&alo.y); av[2] = t.x; av[3] = t.y;
        t = __half22float2(*(__half2*)&alo.z); av[4] = t.x; av[5] = t.y;
        t = __half22float2(*(__half2*)&alo.w); av[6] = t.x; av[7] = t.y;
        t = __half22float2(*(__half2*)&ahi.x); av[8] = t.x; av[9] = t.y;
        t = __half22float2(*(__half2*)&ahi.y); av[10] = t.x; av[11] = t.y;
    }

    const float4* xr = (const float4*)(x + (size_t)i * NPER);
    float xv[NPER];
#pragma unroll
    for (int q = 0; q < 3; q++) {
        float4 v = xr[q];
        xv[q * 4 + 0] = v.x; xv[q * 4 + 1] = v.y;
        xv[q * 4 + 2] = v.z; xv[q * 4 + 3] = v.w;
    }

    float H[4] = {0.f, 0.f, 0.f, 0.f};
#pragma unroll
    for (int p = 0; p < NPER; p++) {
        float sp = fmaf(dinv, av[p], d2 * xv[p]);  // edge sum + self loop (fp32)
        float w = pr[p];
#pragma unroll
        for (int c = 0; c < 4; c++) {
            float zc = fsigmoid(fmaf(sp, az[c], bz[c]));
            float th = ftanh(fmaf(sp, ah[c], bh[c]));
            H[c] = fmaf(w * (1.0f - zc), th, H[c]);
        }
    }

    float o[NPER];
#pragma unroll
    for (int f = 0; f < NPER; f++) {
        float v = __ldg(&ob[f]);
#pragma unroll
        for (int c = 0; c < 4; c++) v = fmaf(H[c], __ldg(&ow[c * NPER + f]), v);
        o[f] = v;
    }
    float4* orow = (float4*)(out + (size_t)i * NPER);
    orow[0] = make_float4(o[0], o[1], o[2], o[3]);
    orow[1] = make_float4(o[4], o[5], o[6], o[7]);
    orow[2] = make_float4(o[8], o[9], o[10], o[11]);
}

// ---------------- launch ----------------
extern "C" void kernel_launch(void* const* d_in, const int* in_sizes, int n_in,
                              void* d_out, int out_size) {
    const float* x  = (const float*)d_in[0];
    const int*   ei = (const int*)d_in[1];
    const float* cz_w = (const float*)d_in[2];
    const float* cz_b = (const float*)d_in[3];
    const float* lz_w = (const float*)d_in[4];
    const float* lz_b = (const float*)d_in[5];
    // d_in[6..9] = conv_r / lin_r : dead (multiplied by H0 == 0)
    const float* ch_w = (const float*)d_in[10];
    const float* ch_b = (const float*)d_in[11];
    const float* lh_w = (const float*)d_in[12];
    const float* lh_b = (const float*)d_in[13];
    const float* att  = (const float*)d_in[14];
    const float* ow   = (const float*)d_in[15];
    const float* ob   = (const float*)d_in[16];
    float* out = (float*)d_out;

    int N = in_sizes[0] / NPER;
    int E = in_sizes[1] / 2;
    const int* src = ei;
    const int* dst = ei + E;

    const int TB = 256;
    int q4 = (E >> 2) + 1;
    k_deg<<<(q4 + TB - 1) / TB, TB>>>(dst, E, cz_w, cz_b, lz_w, lz_b,
                                      ch_w, ch_b, lh_w, lh_b, att);
    k_prep<<<(N + TB - 1) / TB, TB>>>(x, N);
    k_scatter<<<(q4 + TB - 1) / TB, TB>>>(src, dst, E);
    k_final<<<(N + TB - 1) / TB, TB>>>(x, ow, ob, out, N);
}

// round 7
// speedup vs baseline: 1.0832x; 1.0496x over previous
#include <cuda_runtime.h>
#include <cuda_fp16.h>

#define NODES_MAX 100000
#define NPER 12
#define ROWH 16   // padded fp16 row: 16 halves = 32 B = one L2 sector

__device__ int    g_deg[NODES_MAX];          // zero-init at load; k_final re-zeroes each call
__device__ float  g_dinv[NODES_MAX];
__device__ __align__(32) __half g_yh[NODES_MAX * ROWH];    // y = x * dinv_src, fp16
__device__ __align__(32) __half g_acch[NODES_MAX * ROWH];  // fp16 accumulator
// folded coefficients: azh[4] (=az/2), bzh[4] (=bz/2), ah[4], bh[4], wh[12] (=softmax/2)
__device__ float g_cf[32];

// ---------------- K1: degree count (int4 vectorized) + coef fold ----------------
__global__ void k_deg(const int* __restrict__ dst, int E,
                      const float* __restrict__ cz_w, const float* __restrict__ cz_b,
                      const float* __restrict__ lz_w, const float* __restrict__ lz_b,
                      const float* __restrict__ ch_w, const float* __restrict__ ch_b,
                      const float* __restrict__ lh_w, const float* __restrict__ lh_b,
                      const float* __restrict__ att) {
    int i = blockIdx.x * blockDim.x + threadIdx.x;
    int e4 = E >> 2;
    if (i < e4) {
        int4 d = ((const int4*)dst)[i];
        atomicAdd(&g_deg[d.x], 1);
        atomicAdd(&g_deg[d.y], 1);
        atomicAdd(&g_deg[d.z], 1);
        atomicAdd(&g_deg[d.w], 1);
    } else if (i == e4) {
        for (int r = e4 * 4; r < E; r++) atomicAdd(&g_deg[dst[r]], 1);
    }
    if (blockIdx.x == 0 && threadIdx.x == 0) {
        // fold rank-1 GCN + linear into affine pairs per gate/channel
        for (int c = 0; c < 4; c++) {
            float a = 0.f, b = lz_b[c];
            float a2 = 0.f, b2 = lh_b[c];
            for (int k = 0; k < 4; k++) {
                float lz = lz_w[k * 4 + c];
                float lh = lh_w[k * 4 + c];
                a  += cz_w[k] * lz;
                b  += cz_b[k] * lz;
                a2 += ch_w[k] * lh;
                b2 += ch_b[k] * lh;
            }
            g_cf[c]     = 0.5f * a;   // halved: sigmoid(x) = 0.5 + 0.5*tanh(x/2)
            g_cf[4 + c] = 0.5f * b;
            g_cf[8 + c]  = a2;
            g_cf[12 + c] = b2;
        }
        float m = -1e30f;
        for (int p = 0; p < NPER; p++) m = fmaxf(m, att[p]);
        float sum = 0.f;
        float e[NPER];
        for (int p = 0; p < NPER; p++) { e[p] = __expf(att[p] - m); sum += e[p]; }
        float inv = 0.5f / sum;  // halved: absorbs the 0.5 from (1-z) = 0.5*(1-t1)
        for (int p = 0; p < NPER; p++) g_cf[16 + p] = e[p] * inv;
    }
}

// ---------------- K2: dinv + scaled x into padded fp16 rows (+ zero acc) ----------------
__global__ void k_prep(const float* __restrict__ x, int n) {
    int i = blockIdx.x * blockDim.x + threadIdx.x;
    if (i >= n) return;
    float dinv = rsqrtf((float)(g_deg[i] + 1));  // +1 for self loop
    g_dinv[i] = dinv;
    const float4* xr = (const float4*)(x + (size_t)i * NPER);
    float4 a = xr[0], b = xr[1], c = xr[2];
    __half2 h0 = __floats2half2_rn(a.x * dinv, a.y * dinv);
    __half2 h1 = __floats2half2_rn(a.z * dinv, a.w * dinv);
    __half2 h2 = __floats2half2_rn(b.x * dinv, b.y * dinv);
    __half2 h3 = __floats2half2_rn(b.z * dinv, b.w * dinv);
    __half2 h4 = __floats2half2_rn(c.x * dinv, c.y * dinv);
    __half2 h5 = __floats2half2_rn(c.z * dinv, c.w * dinv);
    uint4* row = (uint4*)(g_yh + (size_t)i * ROWH);
    uint4 lo;
    lo.x = *(unsigned*)&h0;
    lo.y = *(unsigned*)&h1;
    lo.z = *(unsigned*)&h2;
    lo.w = *(unsigned*)&h3;
    row[0] = lo;
    uint4 hi;
    hi.x = *(unsigned*)&h4;
    hi.y = *(unsigned*)&h5;
    hi.z = 0;
    hi.w = 0;
    row[1] = hi;
    uint4* arow = (uint4*)(g_acch + (size_t)i * ROWH);
    arow[0] = make_uint4(0, 0, 0, 0);
    arow[1] = make_uint4(0, 0, 0, 0);
}

// ---------------- K3: edge scatter, 8 edges/thread ----------------
__device__ __forceinline__ void scatter_one(int d, uint4 lo, uint2 hi) {
    __half* ap = g_acch + (size_t)d * ROWH;
    asm volatile("red.global.add.noftz.v4.f16x2 [%0], {%1,%2,%3,%4};"
                 :: "l"(ap), "r"(lo.x), "r"(lo.y), "r"(lo.z), "r"(lo.w)
                 : "memory");
    asm volatile("red.global.add.noftz.v2.f16x2 [%0], {%1,%2};"
                 :: "l"(ap + 8), "r"(hi.x), "r"(hi.y)
                 : "memory");
}

__global__ void k_scatter(const int* __restrict__ src, const int* __restrict__ dst, int E) {
    int t = blockIdx.x * blockDim.x + threadIdx.x;
    int e8 = E >> 3;
    if (t < e8) {
        int4 sA = ((const int4*)src)[2 * t];
        int4 sB = ((const int4*)src)[2 * t + 1];
        int4 dA = ((const int4*)dst)[2 * t];
        int4 dB = ((const int4*)dst)[2 * t + 1];
        const uint4* y0 = (const uint4*)(g_yh + (size_t)sA.x * ROWH);
        const uint4* y1 = (const uint4*)(g_yh + (size_t)sA.y * ROWH);
        const uint4* y2 = (const uint4*)(g_yh + (size_t)sA.z * ROWH);
        const uint4* y3 = (const uint4*)(g_yh + (size_t)sA.w * ROWH);
        const uint4* y4 = (const uint4*)(g_yh + (size_t)sB.x * ROWH);
        const uint4* y5 = (const uint4*)(g_yh + (size_t)sB.y * ROWH);
        const uint4* y6 = (const uint4*)(g_yh + (size_t)sB.z * ROWH);
        const uint4* y7 = (const uint4*)(g_yh + (size_t)sB.w * ROWH);
        uint4 lo0 = __ldg(y0); uint2 hi0 = __ldg((const uint2*)(y0 + 1));
        uint4 lo1 = __ldg(y1); uint2 hi1 = __ldg((const uint2*)(y1 + 1));
        uint4 lo2 = __ldg(y2); uint2 hi2 = __ldg((const uint2*)(y2 + 1));
        uint4 lo3 = __ldg(y3); uint2 hi3 = __ldg((const uint2*)(y3 + 1));
        uint4 lo4 = __ldg(y4); uint2 hi4 = __ldg((const uint2*)(y4 + 1));
        uint4 lo5 = __ldg(y5); uint2 hi5 = __ldg((const uint2*)(y5 + 1));
        uint4 lo6 = __ldg(y6); uint2 hi6 = __ldg((const uint2*)(y6 + 1));
        uint4 lo7 = __ldg(y7); uint2 hi7 = __ldg((const uint2*)(y7 + 1));
        scatter_one(dA.x, lo0, hi0);
        scatter_one(dA.y, lo1, hi1);
        scatter_one(dA.z, lo2, hi2);
        scatter_one(dA.w, lo3, hi3);
        scatter_one(dB.x, lo4, hi4);
        scatter_one(dB.y, lo5, hi5);
        scatter_one(dB.z, lo6, hi6);
        scatter_one(dB.w, lo7, hi7);
    } else if (t == e8) {
        for (int r = e8 * 8; r < E; r++) {
            int s = src[r], d = dst[r];
            const uint4* yr = (const uint4*)(g_yh + (size_t)s * ROWH);
            uint4 lo = __ldg(yr); uint2 hi = __ldg((const uint2*)(yr + 1));
            scatter_one(d, lo, hi);
        }
    }
}

// ---------------- K4: per-node epilogue (+ re-zero deg for next call) ----------------
__device__ __forceinline__ float tanh_fast(float x) {
    float y;
    asm("tanh.approx.f32 %0, %1;" : "=f"(y) : "f"(x));
    return y;
}

__global__ void k_final(const float* __restrict__ x,
                        const float* __restrict__ ow, const float* __restrict__ ob,
                        float* __restrict__ out, int n) {
    int i = blockIdx.x * blockDim.x + threadIdx.x;
    if (i >= n) return;

    g_deg[i] = 0;  // leave deg zeroed for the next kernel_launch call

    float azh[4], bzh[4], ah[4], bh[4], wh[NPER];
#pragma unroll
    for (int c = 0; c < 4; c++) {
        azh[c] = __ldg(&g_cf[c]);
        bzh[c] = __ldg(&g_cf[4 + c]);
        ah[c]  = __ldg(&g_cf[8 + c]);
        bh[c]  = __ldg(&g_cf[12 + c]);
    }
#pragma unroll
    for (int p = 0; p < NPER; p++) wh[p] = __ldg(&g_cf[16 + p]);

    float dinv = g_dinv[i];
    float d2 = dinv * dinv;

    const uint4* ar = (const uint4*)(g_acch + (size_t)i * ROWH);
    uint4 alo = ar[0];
    uint2 ahi = *(const uint2*)(ar + 1);
    float av[NPER];
    {
        float2 t;
        t = __half22float2(*(__half2*)&alo.x); av[0] = t.x; av[1] = t.y;
        t = __half22float2(*(__half2*)&alo.y); av[2] = t.x; av[3] = t.y;
        t = __half22float2(*(__half2*)&alo.z); av[4] = t.x; av[5] = t.y;
        t = __half22float2(*(__half2*)&alo.w); av[6] = t.x; av[7] = t.y;
        t = __half22float2(*(__half2*)&ahi.x); av[8] = t.x; av[9] = t.y;
        t = __half22float2(*(__half2*)&ahi.y); av[10] = t.x; av[11] = t.y;
    }

    const float4* xr = (const float4*)(x + (size_t)i * NPER);
    float xv[NPER];
#pragma unroll
    for (int q = 0; q < 3; q++) {
        float4 v = xr[q];
        xv[q * 4 + 0] = v.x; xv[q * 4 + 1] = v.y;
        xv[q * 4 + 2] = v.z; xv[q * 4 + 3] = v.w;
    }

    float H[4] = {0.f, 0.f, 0.f, 0.f};
#pragma unroll
    for (int p = 0; p < NPER; p++) {
        float sp = fmaf(dinv, av[p], d2 * xv[p]);  // edge sum + self loop (fp32)
        float w = wh[p];                            // = softmax_p / 2
#pragma unroll
        for (int c = 0; c < 4; c++) {
            // sigmoid(u) = 0.5 + 0.5*tanh(u/2);  1-z = 0.5*(1 - t1)
            float t1 = tanh_fast(fmaf(sp, azh[c], bzh[c]));
            float t2 = tanh_fast(fmaf(sp, ah[c], bh[c]));
            H[c] = fmaf(w * (1.0f - t1), t2, H[c]);
        }
    }

    float o[NPER];
#pragma unroll
    for (int f = 0; f < NPER; f++) {
        float v = __ldg(&ob[f]);
#pragma unroll
        for (int c = 0; c < 4; c++) v = fmaf(H[c], __ldg(&ow[c * NPER + f]), v);
        o[f] = v;
    }
    float4* orow = (float4*)(out + (size_t)i * NPER);
    orow[0] = make_float4(o[0], o[1], o[2], o[3]);
    orow[1] = make_float4(o[4], o[5], o[6], o[7]);
    orow[2] = make_float4(o[8], o[9], o[10], o[11]);
}

// ---------------- launch ----------------
extern "C" void kernel_launch(void* const* d_in, const int* in_sizes, int n_in,
                              void* d_out, int out_size) {
    const float* x  = (const float*)d_in[0];
    const int*   ei = (const int*)d_in[1];
    const float* cz_w = (const float*)d_in[2];
    const float* cz_b = (const float*)d_in[3];
    const float* lz_w = (const float*)d_in[4];
    const float* lz_b = (const float*)d_in[5];
    // d_in[6..9] = conv_r / lin_r : dead (multiplied by H0 == 0)
    const float* ch_w = (const float*)d_in[10];
    const float* ch_b = (const float*)d_in[11];
    const float* lh_w = (const float*)d_in[12];
    const float* lh_b = (const float*)d_in[13];
    const float* att  = (const float*)d_in[14];
    const float* ow   = (const float*)d_in[15];
    const float* ob   = (const float*)d_in[16];
    float* out = (float*)d_out;

    int N = in_sizes[0] / NPER;
    int E = in_sizes[1] / 2;
    const int* src = ei;
    const int* dst = ei + E;

    const int TB = 256;
    int q4 = (E >> 2) + 1;
    int q8 = (E >> 3) + 1;
    k_deg<<<(q4 + TB - 1) / TB, TB>>>(dst, E, cz_w, cz_b, lz_w, lz_b,
                                      ch_w, ch_b, lh_w, lh_b, att);
    k_prep<<<(N + TB - 1) / TB, TB>>>(x, N);
    k_scatter<<<(q8 + TB - 1) / TB, TB>>>(src, dst, E);
    k_final<<<(N + TB - 1) / TB, TB>>>(x, ow, ob, out, N);
}